// round 16
// baseline (speedup 1.0000x reference)
#include <cuda_runtime.h>
#include <math.h>

// A=16, NA=8, D_OBS=64, DZ=72, Bn=128.
// Output: value[262144] | weight_z[32768] | weights_obsz[524288]

#define NT1 512
#define NT2 256

// ---------------- cross-launch intermediates ----------------
__device__ float g_w   [32768];
__device__ float g_wo  [32768];
__device__ float g_u_av[2048*64];
__device__ float g_v_av[2048*64];
__device__ float g_U   [2048*64];
__device__ float g_FmP [2048*64];
__device__ float g_Ct  [64*65];
__device__ float g_fb  [64];

__device__ __forceinline__ float leaky(float x){ return x > 0.f ? x : 0.01f*x; }

#define PACK2(out, lo, hi) \
    asm("mov.b64 %0, {%1, %2};" : "=l"(out) : "r"(lo), "r"(hi))
#define FMA2(acc, a, b) \
    asm("fma.rn.f32x2 %0, %1, %2, %0;" : "+l"(acc) : "l"(a), "l"(b))

__device__ __forceinline__ void load_wT(const float* __restrict__ w, int in_n, float* wt){
    for (int idx = threadIdx.x; idx < 64*in_n; idx += blockDim.x) {
        int t = idx / in_n, c = idx - t*in_n;
        wt[c*65 + t] = w[idx];
    }
}

// Dual-weight GEMM: one input, two weight sets. 16 rows x 64 outs, NT threads.
template<int NT, int CIN, int LDIN, bool LKA, bool LKB>
__device__ __forceinline__ void g16_2w(const float* __restrict__ in_s,
                                       const float* __restrict__ wA, const float* __restrict__ bA,
                                       float* __restrict__ oA,
                                       const float* __restrict__ wB, const float* __restrict__ bB,
                                       float* __restrict__ oB)
{
    constexpr int RPG = 16 / (NT/64);
    int t  = threadIdx.x & 63;
    int rg = threadIdx.x >> 6;
    float accA[RPG], accB[RPG];
    float biasA = bA ? bA[t] : 0.f, biasB = bB ? bB[t] : 0.f;
    #pragma unroll
    for (int k = 0; k < RPG; k++){ accA[k] = biasA; accB[k] = biasB; }
    #pragma unroll
    for (int c4 = 0; c4 < CIN/4; c4++) {
        float a0 = wA[(c4*4+0)*65 + t], a1 = wA[(c4*4+1)*65 + t];
        float a2 = wA[(c4*4+2)*65 + t], a3 = wA[(c4*4+3)*65 + t];
        float b0 = wB[(c4*4+0)*65 + t], b1 = wB[(c4*4+1)*65 + t];
        float b2 = wB[(c4*4+2)*65 + t], b3 = wB[(c4*4+3)*65 + t];
        #pragma unroll
        for (int k = 0; k < RPG; k++) {
            float4 v = *reinterpret_cast<const float4*>(&in_s[(rg*RPG+k)*LDIN + c4*4]);
            accA[k] = fmaf(v.x,a0, fmaf(v.y,a1, fmaf(v.z,a2, fmaf(v.w,a3, accA[k]))));
            accB[k] = fmaf(v.x,b0, fmaf(v.y,b1, fmaf(v.z,b2, fmaf(v.w,b3, accB[k]))));
        }
    }
    #pragma unroll
    for (int k = 0; k < RPG; k++) {
        oA[(rg*RPG+k)*64 + t] = LKA ? leaky(accA[k]) : accA[k];
        oB[(rg*RPG+k)*64 + t] = LKB ? leaky(accB[k]) : accB[k];
    }
}

// Dual-io GEMM: two inputs, two weight sets. 16 rows x 64 outs.
template<int NT, int CIN, bool LKA, bool LKB>
__device__ __forceinline__ void g16_2io(const float* __restrict__ inA,
                                        const float* __restrict__ wA, const float* __restrict__ bA,
                                        float* __restrict__ oA,
                                        const float* __restrict__ inB,
                                        const float* __restrict__ wB, const float* __restrict__ bB,
                                        float* __restrict__ oB)
{
    constexpr int RPG = 16 / (NT/64);
    int t  = threadIdx.x & 63;
    int rg = threadIdx.x >> 6;
    float accA[RPG], accB[RPG];
    float biasA = bA ? bA[t] : 0.f, biasB = bB ? bB[t] : 0.f;
    #pragma unroll
    for (int k = 0; k < RPG; k++){ accA[k] = biasA; accB[k] = biasB; }
    #pragma unroll
    for (int c4 = 0; c4 < CIN/4; c4++) {
        float a0 = wA[(c4*4+0)*65 + t], a1 = wA[(c4*4+1)*65 + t];
        float a2 = wA[(c4*4+2)*65 + t], a3 = wA[(c4*4+3)*65 + t];
        float b0 = wB[(c4*4+0)*65 + t], b1 = wB[(c4*4+1)*65 + t];
        float b2 = wB[(c4*4+2)*65 + t], b3 = wB[(c4*4+3)*65 + t];
        #pragma unroll
        for (int k = 0; k < RPG; k++) {
            float4 va = *reinterpret_cast<const float4*>(&inA[(rg*RPG+k)*64 + c4*4]);
            float4 vb = *reinterpret_cast<const float4*>(&inB[(rg*RPG+k)*64 + c4*4]);
            accA[k] = fmaf(va.x,a0, fmaf(va.y,a1, fmaf(va.z,a2, fmaf(va.w,a3, accA[k]))));
            accB[k] = fmaf(vb.x,b0, fmaf(vb.y,b1, fmaf(vb.z,b2, fmaf(vb.w,b3, accB[k]))));
        }
    }
    #pragma unroll
    for (int k = 0; k < RPG; k++) {
        oA[(rg*RPG+k)*64 + t] = LKA ? leaky(accA[k]) : accA[k];
        oB[(rg*RPG+k)*64 + t] = LKB ? leaky(accB[k]) : accB[k];
    }
}

// ================= L1 (R14 body + batch offset). b0==0: block 64 = kF0 =================
__global__ void __launch_bounds__(NT1, 1)
L1(const float* __restrict__ obs, const float* __restrict__ pol,
   const float* __restrict__ act,
   const float* kw1, const float* kb1, const float* kw2, const float* kb2,
   const float* qw1, const float* qb1, const float* qw2, const float* qb2,
   const float* ko1, const float* ko1b, const float* ko2, const float* ko2b,
   const float* qo1, const float* qo1b, const float* qo2, const float* qo2b,
   const float* av1, const float* av1b, const float* av2w, const float* av2b,
   const float* fv1, const float* fv1b,
   float* __restrict__ out_wz, int b0)
{
    extern __shared__ float sm[];
    int bx = blockIdx.x;
    int tid = threadIdx.x;

    if (b0 == 0 && bx == 64) {   // ---- kF0 ----
        float* fm  = sm;           // 4096
        float* w2t = sm + 4096;    // 4160
        float* b2  = sm + 8256;    // 64
        for (int idx = tid; idx < 4096; idx += NT1) {
            int t = idx >> 6, c = idx & 63;
            fm[idx] = fv1[t*128 + 64 + c];
            w2t[(idx & 63)*65 + (idx >> 6)] = av2w[idx];
        }
        if (tid < 64) b2[tid] = av2b[tid];
        __syncthreads();
        for (int idx = tid; idx < 4096; idx += NT1) {
            int t = idx & 63, e = idx >> 6;
            float s = 0.f;
            for (int c = 0; c < 64; c++) {
                int cc = (c + t) & 63;
                s = fmaf(fm[t*64 + cc], w2t[e*65 + cc], s);
            }
            g_Ct[e*65 + t] = s;
        }
        if (tid < 64) {
            float s = 0.f;
            for (int c = 0; c < 64; c++) {
                int cc = (c + tid) & 63;
                s = fmaf(fm[tid*64 + cc], b2[cc], s);
            }
            g_fb[tid] = s;
        }
        return;
    }

    int b = b0 + bx;
    float* wA    = sm;             // 4680
    float* wB    = sm + 4680;      // 4680
    float* obs16 = sm + 9360;      // 1024
    float* pol16 = sm + 10384;     // 128
    float* dl    = sm + 10512;     // 128
    float* src   = sm + 10640;     // 1152
    float* op    = sm + 11792;     // 1152
    float* hA    = sm + 12944;     // 1024
    float* hB    = sm + 13968;     // 1024
    float* kz    = sm + 14992;     // 1024  (reused as hC)
    float* qz    = sm + 16016;     // 1024
    float* keyo  = sm + 17040;     // 1024
    float* atts  = sm + 18064;     // 1024
    float* uqo   = sm + 19088;     // 1024
    float* uav   = sm + 20112;     // 1024
    float* vqo   = sm + 21136;     // 1024
    float* vav   = sm + 22160;     // 1024
    float* kq    = sm + 23184;     // 1024
    float* Ps    = sm + 24208;     // 1024
    float* w_sm  = sm + 25232;     // 256
    float* kb_s  = sm + 25488;     // 16
    float* hC    = kz;

    for (int idx = tid; idx < 1024; idx += NT1) obs16[idx] = obs[(size_t)b*1024 + idx];
    if (tid < 128) {
        float p = pol[b*128 + tid];
        pol16[tid] = p;
        dl[tid]    = act[b*128 + tid] - p;
    }
    // S1
    load_wT(kw1, 64, wA); load_wT(qw1, 64, wB);
    __syncthreads();
    g16_2w<NT1,64,64,true,true>(obs16, wA, kb1, hA, wB, qb1, hB);
    __syncthreads();
    // S2
    load_wT(kw2, 64, wA); load_wT(qw2, 64, wB);
    __syncthreads();
    g16_2io<NT1,64,false,false>(hA, wA, kb2, kz, hB, wB, qb2, qz);
    __syncthreads();
    // S3: w = sigmoid(qz.kz / 8)
    if (tid < 256) {
        int i = tid >> 4, j = tid & 15;
        float acc = 0.f;
        #pragma unroll
        for (int d = 0; d < 64; d++) {
            int dd = (d + 2*j) & 63;
            acc = fmaf(qz[i*64 + dd], kz[j*64 + dd], acc);
        }
        float w = 1.f / (1.f + expf(-acc * 0.125f));
        w_sm[tid] = w;
        g_w[b*256 + tid] = w;
        out_wz[b*256 + tid] = w;
    }
    __syncthreads();
    // S4: src/op rows
    for (int idx = tid; idx < 1152; idx += NT1) {
        int r = idx / 72, c = idx - r*72;
        float vs, vo;
        if (c < 64) { float o = obs16[r*64 + c]; vs = o; vo = o; }
        else {
            int n = c - 64;
            float p = pol16[r*8 + n];
            vs = fmaf(w_sm[r*17], dl[r*8 + n], p);
            vo = p;
        }
        src[idx] = vs; op[idx] = vo;
    }
    // S5
    load_wT(ko1, 72, wA); load_wT(av1, 72, wB);
    __syncthreads();
    g16_2w<NT1,72,72,true,true>(src, wA, ko1b, hA, wB, av1b, hB);
    __syncthreads();
    // S6: wA=qo1, KEEP wB=av1
    load_wT(qo1, 72, wA);
    __syncthreads();
    g16_2w<NT1,72,72,false,false>(op, wA, qo1b, uqo, wB, av1b, uav);
    g16_2w<NT1,8,8,false,false>(dl, wA + 64*65, nullptr, vqo, wB + 64*65, nullptr, vav);
    __syncthreads();
    for (int idx = tid; idx < 1024; idx += NT1) {
        hC[idx] = leaky(uav[idx]);
        g_u_av[b*1024 + idx] = uav[idx];
        g_v_av[b*1024 + idx] = vav[idx];
    }
    // S7
    load_wT(ko2, 64, wA); load_wT(av2w, 64, wB);
    __syncthreads();
    g16_2io<NT1,64,false,false>(hA, wA, ko2b, keyo, hB, wB, av2b, atts);
    __syncthreads();
    // S8: wA=qo2, KEEP wB=av2w
    for (int idx = tid; idx < 4096; idx += NT1) {
        int c = idx >> 6, t = idx & 63;
        wA[c*65 + t] = qo2[idx];
    }
    __syncthreads();
    g16_2io<NT1,64,false,false>(keyo, wA, nullptr, kq, hC, wB, av2b, Ps);
    if (tid < 16) {
        float s = 0.f;
        for (int c = 0; c < 64; c++) {
            int cc = (c + 4*tid) & 63;
            s = fmaf(keyo[tid*64 + cc], qo2b[cc], s);
        }
        kb_s[tid] = s;
    }
    __syncthreads();
    // S9: U, FmP -> global
    for (int idx = tid; idx < 4096; idx += NT1) {
        int t = idx >> 6, c = idx & 63;
        wA[c*65 + t] = fv1[t*128 + c];
        wB[c*65 + t] = fv1[t*128 + 64 + c];
    }
    __syncthreads();
    g16_2io<NT1,64,false,false>(atts, wA, fv1b, g_U + b*1024, Ps, wB, nullptr, g_FmP + b*1024);
    // S10: wo softmax
    if (tid < 256) {
        int i = tid >> 4, j = tid & 15;
        float wv = w_sm[tid];
        float acc = kb_s[i];
        #pragma unroll
        for (int d = 0; d < 64; d++) {
            int dd = (d + 2*j) & 63;
            float h = leaky(fmaf(wv, vqo[j*64 + dd], uqo[j*64 + dd]));
            acc = fmaf(kq[i*64 + dd], h, acc);
        }
        float sc = fminf(fmaxf(acc * 0.125f, -5.f), 5.f);
        float t = expf(sc);
        float mx = t;
        #pragma unroll
        for (int m = 1; m < 16; m <<= 1) mx = fmaxf(mx, __shfl_xor_sync(0xffffffffu, mx, m));
        float e = expf(t - mx), s = e;
        #pragma unroll
        for (int m = 1; m < 16; m <<= 1) s += __shfl_xor_sync(0xffffffffu, s, m);
        g_wo[b*256 + tid] = e / s;
    }
}

// ================= L2 (R14 body + batch offset) =================
__global__ void __launch_bounds__(NT2, 2)
L2(const float* __restrict__ fv2, const float* __restrict__ fv2b,
   float* __restrict__ out_val, float4* __restrict__ out4, int b0)
{
    extern __shared__ float sm[];
    float* Ct_s  = sm;              // 4352
    float* Lr    = sm + 4352;       // 8704 (aliased as Mp)
    float* LLt   = sm + 13056;      // 8448
    float* u_s   = sm + 21504;      // 1024
    float* v_s   = sm + 22528;      // 1024
    float* U_s   = sm + 23552;      // 1040
    float* Fp_s  = sm + 24592;      // 1040
    float* w_s   = sm + 25632;      // 128
    float* wo_s  = sm + 25760;      // 256
    float* wo2   = sm + 26016;      // 256
    float* fb_s  = sm + 26272;      // 64
    float* fv2q  = sm + 26336;      // 512
    float* b2v   = sm + 26848;      // 8
    float* Mp = Lr;

    int bx = blockIdx.x;
    int b  = b0 + (bx >> 1), ih = bx & 1;
    int tid = threadIdx.x;

    for (int idx = tid; idx < 4096; idx += NT2) {
        int e = idx >> 6, t = idx & 63;
        Ct_s[e*68 + t] = g_Ct[e*65 + t];
    }
    for (int idx = tid; idx < 1024; idx += NT2) {
        u_s[idx] = g_u_av[b*1024 + idx];
        v_s[idx] = g_v_av[b*1024 + idx];
        int r = idx >> 6, c = idx & 63;
        U_s [r*65 + c] = g_U  [b*1024 + idx];
        Fp_s[r*65 + c] = g_FmP[b*1024 + idx];
    }
    if (tid < 128) w_s[tid] = g_w[b*256 + ih*128 + tid];
    wo_s[tid] = g_wo[b*256 + tid];
    if (tid < 64)  fb_s[tid] = g_fb[tid];
    for (int idx = tid; idx < 512; idx += NT2)
        fv2q[idx] = fv2[(idx & 7)*64 + (idx >> 3)];
    if (tid < 8)   b2v[tid] = fv2b[tid];
    __syncthreads();
    {
        int j = tid >> 4, k = tid & 15;
        wo2[tid] = (k == j) ? 0.f : wo_s[tid];
    }
    for (int idx = tid; idx < 8192; idx += NT2) {
        int r = idx >> 6, e = idx & 63;
        int j = r & 15;
        Lr[r*68 + e] = leaky(fmaf(w_s[r], v_s[j*64 + e], u_s[j*64 + e]));
    }
    __syncthreads();
    // LL' build
    {
        int eg = tid & 7, rq = tid >> 3;
        int e0 = eg * 8;
        int i4 = rq >> 2;
        int j0 = (rq & 3) * 4;
        int rbase = i4*16 + j0;
        unsigned long long acc0[8], acc1[8];
        #pragma unroll
        for (int m = 0; m < 8; m++){ acc0[m] = 0ull; acc1[m] = 0ull; }
        #pragma unroll
        for (int k = 0; k < 16; k++) {
            float w00 = wo2[(j0+0)*16 + k], w01 = wo2[(j0+1)*16 + k];
            float w10 = wo2[(j0+2)*16 + k], w11 = wo2[(j0+3)*16 + k];
            unsigned long long wp0, wp1;
            PACK2(wp0, __float_as_uint(w00), __float_as_uint(w01));
            PACK2(wp1, __float_as_uint(w10), __float_as_uint(w11));
            const float* lrow = &Lr[(i4*16 + k)*68 + e0];
            float4 la = *reinterpret_cast<const float4*>(lrow);
            float4 lb = *reinterpret_cast<const float4*>(lrow + 4);
            float ls[8] = {la.x, la.y, la.z, la.w, lb.x, lb.y, lb.z, lb.w};
            #pragma unroll
            for (int m = 0; m < 8; m++) {
                unsigned long long lp;
                unsigned int lu = __float_as_uint(ls[m]);
                PACK2(lp, lu, lu);
                FMA2(acc0[m], lp, wp0);
                FMA2(acc1[m], lp, wp1);
            }
        }
        #pragma unroll
        for (int m = 0; m < 8; m++) {
            *reinterpret_cast<ulonglong2*>(&LLt[(e0 + m)*132 + rbase]) =
                make_ulonglong2(acc0[m], acc1[m]);
        }
    }
    __syncthreads();
    // M = LL' @ Ct -> Mp (aliases Lr)
    {
        int tt = tid & 15, rg = tid >> 4;
        int t0 = tt * 4, r0 = rg * 8;
        unsigned long long acc[4][4];
        #pragma unroll
        for (int a = 0; a < 4; a++)
            #pragma unroll
            for (int k = 0; k < 4; k++) acc[a][k] = 0ull;
        #pragma unroll 2
        for (int e = 0; e < 64; e++) {
            float4 ct = *reinterpret_cast<const float4*>(&Ct_s[e*68 + t0]);
            ulonglong2 la = *reinterpret_cast<const ulonglong2*>(&LLt[e*132 + r0]);
            ulonglong2 lb = *reinterpret_cast<const ulonglong2*>(&LLt[e*132 + r0 + 4]);
            unsigned long long lp0 = la.x, lp1 = la.y, lp2 = lb.x, lp3 = lb.y;
            float cts[4] = {ct.x, ct.y, ct.z, ct.w};
            #pragma unroll
            for (int a = 0; a < 4; a++) {
                unsigned int wu = __float_as_uint(cts[a]);
                unsigned long long wp;
                PACK2(wp, wu, wu);
                FMA2(acc[a][0], lp0, wp);
                FMA2(acc[a][1], lp1, wp);
                FMA2(acc[a][2], lp2, wp);
                FMA2(acc[a][3], lp3, wp);
            }
        }
        __syncthreads();
        #pragma unroll
        for (int k = 0; k < 4; k++) {
            uint2 x0 = *reinterpret_cast<uint2*>(&acc[0][k]);
            uint2 x1 = *reinterpret_cast<uint2*>(&acc[1][k]);
            uint2 x2 = *reinterpret_cast<uint2*>(&acc[2][k]);
            uint2 x3 = *reinterpret_cast<uint2*>(&acc[3][k]);
            *reinterpret_cast<float4*>(&Mp[(r0 + 2*k)*68 + t0]) =
                make_float4(__uint_as_float(x0.x), __uint_as_float(x1.x),
                            __uint_as_float(x2.x), __uint_as_float(x3.x));
            *reinterpret_cast<float4*>(&Mp[(r0 + 2*k + 1)*68 + t0]) =
                make_float4(__uint_as_float(x0.y), __uint_as_float(x1.y),
                            __uint_as_float(x2.y), __uint_as_float(x3.y));
        }
    }
    __syncthreads();
    // value head
    {
        int p = tid >> 1, q = tid & 1;
        int i4 = p >> 4, j = p & 15;
        float wjj = wo_s[j*17];
        float vout[8];
        #pragma unroll
        for (int o = 0; o < 8; o++) vout[o] = 0.f;
        #pragma unroll 4
        for (int tt = 0; tt < 32; tt++) {
            int t = q*32 + tt;
            float Mv  = Mp[p*68 + t];
            float fbt = fb_s[t];
            float h = U_s[j*65 + t] + 0.0625f * (Mv + fbt + wjj * (Fp_s[j*65 + t] - fbt));
            float ht = leaky(h);
            float4 f0 = *reinterpret_cast<const float4*>(&fv2q[t*8]);
            float4 f1 = *reinterpret_cast<const float4*>(&fv2q[t*8 + 4]);
            vout[0] = fmaf(f0.x, ht, vout[0]);
            vout[1] = fmaf(f0.y, ht, vout[1]);
            vout[2] = fmaf(f0.z, ht, vout[2]);
            vout[3] = fmaf(f0.w, ht, vout[3]);
            vout[4] = fmaf(f1.x, ht, vout[4]);
            vout[5] = fmaf(f1.y, ht, vout[5]);
            vout[6] = fmaf(f1.z, ht, vout[6]);
            vout[7] = fmaf(f1.w, ht, vout[7]);
        }
        #pragma unroll
        for (int o = 0; o < 8; o++) vout[o] += __shfl_xor_sync(0xffffffffu, vout[o], 1);
        if (q == 0) {
            #pragma unroll
            for (int o = 0; o < 8; o++) vout[o] += b2v[o];
            int ig = ih*8 + i4;
            float4* dst = reinterpret_cast<float4*>(out_val + (size_t)(b*256 + ig*16 + j)*8);
            dst[0] = make_float4(vout[0], vout[1], vout[2], vout[3]);
            dst[1] = make_float4(vout[4], vout[5], vout[6], vout[7]);
        }
    }
    // weights_obsz half
    {
        const float4* wo4 = reinterpret_cast<const float4*>(wo_s);
        #pragma unroll
        for (int k = 0; k < 2; k++) {
            int q4 = ih*512 + k*256 + tid;
            out4[b*1024 + q4] = wo4[q4 & 63];
        }
    }
}

// ---------------- launcher: batch-halved fork-join overlap ----------------
extern "C" void kernel_launch(void* const* d_in, const int* in_sizes, int n_in,
                              void* d_out, int out_size)
{
    const float* obs  = (const float*)d_in[0];
    const float* pol  = (const float*)d_in[1];
    const float* act  = (const float*)d_in[2];
    const float* kw1  = (const float*)d_in[3];  const float* kw1b = (const float*)d_in[4];
    const float* kw2  = (const float*)d_in[5];  const float* kw2b = (const float*)d_in[6];
    const float* qw1  = (const float*)d_in[7];  const float* qw1b = (const float*)d_in[8];
    const float* qw2  = (const float*)d_in[9];  const float* qw2b = (const float*)d_in[10];
    const float* ko1  = (const float*)d_in[11]; const float* ko1b = (const float*)d_in[12];
    const float* ko2  = (const float*)d_in[13]; const float* ko2b = (const float*)d_in[14];
    const float* qo1  = (const float*)d_in[15]; const float* qo1b = (const float*)d_in[16];
    const float* qo2  = (const float*)d_in[17]; const float* qo2b = (const float*)d_in[18];
    const float* av1  = (const float*)d_in[19]; const float* av1b = (const float*)d_in[20];
    const float* av2  = (const float*)d_in[21]; const float* av2b = (const float*)d_in[22];
    const float* fv1  = (const float*)d_in[23]; const float* fv1b = (const float*)d_in[24];
    const float* fv2  = (const float*)d_in[25]; const float* fv2b = (const float*)d_in[26];

    float* out      = (float*)d_out;
    float* out_val  = out;
    float* out_wz   = out + 262144;
    float* out_obsz = out + 294912;

    const int SM1 = 25504 * 4;   // 102016
    const int SM2 = 26856 * 4;   // 107424

    cudaFuncSetAttribute(L1, cudaFuncAttributeMaxDynamicSharedMemorySize, SM1);
    cudaFuncSetAttribute(L2, cudaFuncAttributeMaxDynamicSharedMemorySize, SM2);

    // fresh fork stream + events each call (host objects only; no device allocs)
    cudaStream_t s2;
    cudaEvent_t evA, evB, evJ;
    cudaStreamCreateWithFlags(&s2, cudaStreamNonBlocking);
    cudaEventCreateWithFlags(&evA, cudaEventDisableTiming);
    cudaEventCreateWithFlags(&evB, cudaEventDisableTiming);
    cudaEventCreateWithFlags(&evJ, cudaEventDisableTiming);

    // L1a: batches [0,64) + kF0 (block 64)
    L1<<<65, NT1, SM1>>>(obs, pol, act,
                         kw1, kw1b, kw2, kw2b, qw1, qw1b, qw2, qw2b,
                         ko1, ko1b, ko2, ko2b, qo1, qo1b, qo2, qo2b,
                         av1, av1b, av2, av2b, fv1, fv1b, out_wz, 0);
    cudaEventRecord(evA, 0);
    // L1b: batches [64,128) — overlaps with L2a on s2
    L1<<<64, NT1, SM1>>>(obs, pol, act,
                         kw1, kw1b, kw2, kw2b, qw1, qw1b, qw2, qw2b,
                         ko1, ko1b, ko2, ko2b, qo1, qo1b, qo2, qo2b,
                         av1, av1b, av2, av2b, fv1, fv1b, out_wz, 64);
    cudaEventRecord(evB, 0);

    cudaStreamWaitEvent(s2, evA, 0);
    L2<<<128, NT2, SM2, s2>>>(fv2, fv2b, out_val,
                              reinterpret_cast<float4*>(out_obsz), 0);
    cudaStreamWaitEvent(s2, evB, 0);
    L2<<<128, NT2, SM2, s2>>>(fv2, fv2b, out_val,
                              reinterpret_cast<float4*>(out_obsz), 64);
    cudaEventRecord(evJ, s2);
    cudaStreamWaitEvent((cudaStream_t)0, evJ, 0);
}

// round 17
// speedup vs baseline: 1.3651x; 1.3651x over previous
#include <cuda_runtime.h>
#include <math.h>

// A=16, NA=8, D_OBS=64, DZ=72, Bn=128.
// Output: value[262144] | weight_z[32768] | weights_obsz[524288]

#define NT1 512
#define NT2 256

// ---------------- cross-launch intermediates ----------------
__device__ float g_w   [32768];
__device__ float g_wo  [32768];
__device__ float g_u_av[2048*64];
__device__ float g_v_av[2048*64];
__device__ float g_U   [2048*64];
__device__ float g_FmP [2048*64];
__device__ float g_Ct  [64*65];
__device__ float g_fb  [64];

__device__ __forceinline__ float leaky(float x){ return x > 0.f ? x : 0.01f*x; }

#define PACK2(out, lo, hi) \
    asm("mov.b64 %0, {%1, %2};" : "=l"(out) : "r"(lo), "r"(hi))
#define FMA2(acc, a, b) \
    asm("fma.rn.f32x2 %0, %1, %2, %0;" : "+l"(acc) : "l"(a), "l"(b))

// t-major padded weight copy: wt[t*ws + c] = w[t*in_n + c]. in_n % 4 == 0.
__device__ __forceinline__ void load_w(const float* __restrict__ w, int in_n, int ws, float* wt){
    int n4 = (64*in_n) >> 2;
    for (int idx = threadIdx.x; idx < n4; idx += blockDim.x) {
        int i = idx << 2;
        int t = i / in_n, c = i - t*in_n;
        float4 v = *reinterpret_cast<const float4*>(w + i);
        *reinterpret_cast<float4*>(&wt[t*ws + c]) = v;
    }
}

// Dual-weight GEMM: one input, two t-major weight sets. 16 rows x 64 outs.
template<int NT, int CIN, int LDIN, int WS, bool LKA, bool LKB>
__device__ __forceinline__ void g16_2w(const float* __restrict__ in_s,
                                       const float* __restrict__ wA, const float* __restrict__ bA,
                                       float* __restrict__ oA,
                                       const float* __restrict__ wB, const float* __restrict__ bB,
                                       float* __restrict__ oB)
{
    constexpr int RPG = 16 / (NT/64);
    int t  = threadIdx.x & 63;
    int rg = threadIdx.x >> 6;
    const float4* wAp = reinterpret_cast<const float4*>(&wA[t*WS]);
    const float4* wBp = reinterpret_cast<const float4*>(&wB[t*WS]);
    float accA[RPG], accB[RPG];
    float biasA = bA ? bA[t] : 0.f, biasB = bB ? bB[t] : 0.f;
    #pragma unroll
    for (int k = 0; k < RPG; k++){ accA[k] = biasA; accB[k] = biasB; }
    #pragma unroll
    for (int c4 = 0; c4 < CIN/4; c4++) {
        float4 a = wAp[c4];
        float4 b = wBp[c4];
        #pragma unroll
        for (int k = 0; k < RPG; k++) {
            float4 v = *reinterpret_cast<const float4*>(&in_s[(rg*RPG+k)*LDIN + c4*4]);
            accA[k] = fmaf(v.x,a.x, fmaf(v.y,a.y, fmaf(v.z,a.z, fmaf(v.w,a.w, accA[k]))));
            accB[k] = fmaf(v.x,b.x, fmaf(v.y,b.y, fmaf(v.z,b.z, fmaf(v.w,b.w, accB[k]))));
        }
    }
    #pragma unroll
    for (int k = 0; k < RPG; k++) {
        oA[(rg*RPG+k)*64 + t] = LKA ? leaky(accA[k]) : accA[k];
        oB[(rg*RPG+k)*64 + t] = LKB ? leaky(accB[k]) : accB[k];
    }
}

// Dual-io GEMM: two inputs, two t-major weight sets. 16 rows x 64 outs.
template<int NT, int CIN, int WS, bool LKA, bool LKB>
__device__ __forceinline__ void g16_2io(const float* __restrict__ inA,
                                        const float* __restrict__ wA, const float* __restrict__ bA,
                                        float* __restrict__ oA,
                                        const float* __restrict__ inB,
                                        const float* __restrict__ wB, const float* __restrict__ bB,
                                        float* __restrict__ oB)
{
    constexpr int RPG = 16 / (NT/64);
    int t  = threadIdx.x & 63;
    int rg = threadIdx.x >> 6;
    const float4* wAp = reinterpret_cast<const float4*>(&wA[t*WS]);
    const float4* wBp = reinterpret_cast<const float4*>(&wB[t*WS]);
    float accA[RPG], accB[RPG];
    float biasA = bA ? bA[t] : 0.f, biasB = bB ? bB[t] : 0.f;
    #pragma unroll
    for (int k = 0; k < RPG; k++){ accA[k] = biasA; accB[k] = biasB; }
    #pragma unroll
    for (int c4 = 0; c4 < CIN/4; c4++) {
        float4 a = wAp[c4];
        float4 b = wBp[c4];
        #pragma unroll
        for (int k = 0; k < RPG; k++) {
            float4 va = *reinterpret_cast<const float4*>(&inA[(rg*RPG+k)*64 + c4*4]);
            float4 vb = *reinterpret_cast<const float4*>(&inB[(rg*RPG+k)*64 + c4*4]);
            accA[k] = fmaf(va.x,a.x, fmaf(va.y,a.y, fmaf(va.z,a.z, fmaf(va.w,a.w, accA[k]))));
            accB[k] = fmaf(vb.x,b.x, fmaf(vb.y,b.y, fmaf(vb.z,b.z, fmaf(vb.w,b.w, accB[k]))));
        }
    }
    #pragma unroll
    for (int k = 0; k < RPG; k++) {
        oA[(rg*RPG+k)*64 + t] = LKA ? leaky(accA[k]) : accA[k];
        oB[(rg*RPG+k)*64 + t] = LKB ? leaky(accB[k]) : accB[k];
    }
}

// ================= L1: one block per batch (512 thr); block 128 = kF0 =================
__global__ void __launch_bounds__(NT1, 1)
L1(const float* __restrict__ obs, const float* __restrict__ pol,
   const float* __restrict__ act,
   const float* kw1, const float* kb1, const float* kw2, const float* kb2,
   const float* qw1, const float* qb1, const float* qw2, const float* qb2,
   const float* ko1, const float* ko1b, const float* ko2, const float* ko2b,
   const float* qo1, const float* qo1b, const float* qo2, const float* qo2b,
   const float* av1, const float* av1b, const float* av2w, const float* av2b,
   const float* fv1, const float* fv1b,
   float* __restrict__ out_wz)
{
    extern __shared__ float sm[];
    int bx = blockIdx.x;
    int tid = threadIdx.x;

    if (bx == 128) {   // ---- kF0 ----
        float* fm  = sm;           // 4096
        float* w2t = sm + 4096;    // 4160
        float* b2  = sm + 8256;    // 64
        for (int idx = tid; idx < 4096; idx += NT1) {
            int t = idx >> 6, c = idx & 63;
            fm[idx] = fv1[t*128 + 64 + c];
            w2t[(idx & 63)*65 + (idx >> 6)] = av2w[idx];
        }
        if (tid < 64) b2[tid] = av2b[tid];
        __syncthreads();
        for (int idx = tid; idx < 4096; idx += NT1) {
            int t = idx & 63, e = idx >> 6;
            float s = 0.f;
            for (int c = 0; c < 64; c++) {
                int cc = (c + t) & 63;
                s = fmaf(fm[t*64 + cc], w2t[e*65 + cc], s);
            }
            g_Ct[e*65 + t] = s;
        }
        if (tid < 64) {
            float s = 0.f;
            for (int c = 0; c < 64; c++) {
                int cc = (c + tid) & 63;
                s = fmaf(fm[tid*64 + cc], b2[cc], s);
            }
            g_fb[tid] = s;
        }
        return;
    }

    int b = bx;
    // t-major weight buffers: max row stride 100 (CIN=72)
    float* wA    = sm;             // 6400
    float* wB    = sm + 6400;      // 6400
    float* obs16 = sm + 12800;     // 1024
    float* pol16 = sm + 13824;     // 128
    float* dl    = sm + 13952;     // 128
    float* src   = sm + 14080;     // 1152
    float* op    = sm + 15232;     // 1152
    float* hA    = sm + 16384;     // 1024
    float* hB    = sm + 17408;     // 1024
    float* kz    = sm + 18432;     // 1024 (hC alias)
    float* qz    = sm + 19456;     // 1024
    float* keyo  = sm + 20480;     // 1024
    float* atts  = sm + 21504;     // 1024
    float* uqo   = sm + 22528;     // 1024
    float* uav   = sm + 23552;     // 1024
    float* vqo   = sm + 24576;     // 1024
    float* vav   = sm + 25600;     // 1024
    float* kq    = sm + 26624;     // 1024
    float* Ps    = sm + 27648;     // 1024
    float* w_sm  = sm + 28672;     // 256
    float* kb_s  = sm + 28928;     // 16
    float* hC    = kz;
    // total 28944 floats = 115776 B

    for (int idx = tid; idx < 1024; idx += NT1) obs16[idx] = obs[(size_t)b*1024 + idx];
    if (tid < 128) {
        float p = pol[b*128 + tid];
        pol16[tid] = p;
        dl[tid]    = act[b*128 + tid] - p;
    }
    // S1
    load_w(kw1, 64, 68, wA); load_w(qw1, 64, 68, wB);
    __syncthreads();
    g16_2w<NT1,64,64,68,true,true>(obs16, wA, kb1, hA, wB, qb1, hB);
    __syncthreads();
    // S2
    load_w(kw2, 64, 68, wA); load_w(qw2, 64, 68, wB);
    __syncthreads();
    g16_2io<NT1,64,68,false,false>(hA, wA, kb2, kz, hB, wB, qb2, qz);
    __syncthreads();
    // S3: w = sigmoid(qz.kz / 8)
    if (tid < 256) {
        int i = tid >> 4, j = tid & 15;
        float acc = 0.f;
        #pragma unroll
        for (int d = 0; d < 64; d++) {
            int dd = (d + 2*j) & 63;
            acc = fmaf(qz[i*64 + dd], kz[j*64 + dd], acc);
        }
        float w = 1.f / (1.f + expf(-acc * 0.125f));
        w_sm[tid] = w;
        g_w[b*256 + tid] = w;
        out_wz[b*256 + tid] = w;
    }
    __syncthreads();
    // S4: src/op rows
    for (int idx = tid; idx < 1152; idx += NT1) {
        int r = idx / 72, c = idx - r*72;
        float vs, vo;
        if (c < 64) { float o = obs16[r*64 + c]; vs = o; vo = o; }
        else {
            int n = c - 64;
            float p = pol16[r*8 + n];
            vs = fmaf(w_sm[r*17], dl[r*8 + n], p);
            vo = p;
        }
        src[idx] = vs; op[idx] = vo;
    }
    // S5
    load_w(ko1, 72, 100, wA); load_w(av1, 72, 100, wB);
    __syncthreads();
    g16_2w<NT1,72,72,100,true,true>(src, wA, ko1b, hA, wB, av1b, hB);
    __syncthreads();
    // S6: wA=qo1, KEEP wB=av1 (both stride 100)
    load_w(qo1, 72, 100, wA);
    __syncthreads();
    g16_2w<NT1,72,72,100,false,false>(op, wA, qo1b, uqo, wB, av1b, uav);
    g16_2w<NT1,8,8,100,false,false>(dl, wA + 64, nullptr, vqo, wB + 64, nullptr, vav);
    __syncthreads();
    for (int idx = tid; idx < 1024; idx += NT1) {
        hC[idx] = leaky(uav[idx]);
        g_u_av[b*1024 + idx] = uav[idx];
        g_v_av[b*1024 + idx] = vav[idx];
    }
    // S7
    load_w(ko2, 64, 68, wA); load_w(av2w, 64, 68, wB);
    __syncthreads();
    g16_2io<NT1,64,68,false,false>(hA, wA, ko2b, keyo, hB, wB, av2b, atts);
    __syncthreads();
    // S8: wA = qo2^T (wt[t][c] = qo2[c][t]), KEEP wB=av2w
    for (int idx = tid; idx < 4096; idx += NT1) {
        int c = idx >> 6, t = idx & 63;
        wA[t*68 + c] = qo2[idx];
    }
    __syncthreads();
    g16_2io<NT1,64,68,false,false>(keyo, wA, nullptr, kq, hC, wB, av2b, Ps);
    if (tid < 16) {
        float s = 0.f;
        for (int c = 0; c < 64; c++) {
            int cc = (c + 4*tid) & 63;
            s = fmaf(keyo[tid*64 + cc], qo2b[cc], s);
        }
        kb_s[tid] = s;
    }
    __syncthreads();
    // S9: fv1 slices t-major; U, FmP -> global
    for (int idx = tid; idx < 1024; idx += NT1) {
        int t = idx >> 4, c4 = (idx & 15) << 2;
        *reinterpret_cast<float4*>(&wA[t*68 + c4]) =
            *reinterpret_cast<const float4*>(fv1 + t*128 + c4);
        *reinterpret_cast<float4*>(&wB[t*68 + c4]) =
            *reinterpret_cast<const float4*>(fv1 + t*128 + 64 + c4);
    }
    __syncthreads();
    g16_2io<NT1,64,68,false,false>(atts, wA, fv1b, g_U + b*1024, Ps, wB, nullptr, g_FmP + b*1024);
    // S10: wo softmax
    if (tid < 256) {
        int i = tid >> 4, j = tid & 15;
        float wv = w_sm[tid];
        float acc = kb_s[i];
        #pragma unroll
        for (int d = 0; d < 64; d++) {
            int dd = (d + 2*j) & 63;
            float h = leaky(fmaf(wv, vqo[j*64 + dd], uqo[j*64 + dd]));
            acc = fmaf(kq[i*64 + dd], h, acc);
        }
        float sc = fminf(fmaxf(acc * 0.125f, -5.f), 5.f);
        float t = expf(sc);
        float mx = t;
        #pragma unroll
        for (int m = 1; m < 16; m <<= 1) mx = fmaxf(mx, __shfl_xor_sync(0xffffffffu, mx, m));
        float e = expf(t - mx), s = e;
        #pragma unroll
        for (int m = 1; m < 16; m <<= 1) s += __shfl_xor_sync(0xffffffffu, s, m);
        g_wo[b*256 + tid] = e / s;
    }
}

// ================= L2: wo folded pre-GEMM (LL'), register-tiled f32x2 (R14) =================
__global__ void __launch_bounds__(NT2, 2)
L2(const float* __restrict__ fv2, const float* __restrict__ fv2b,
   float* __restrict__ out_val, float4* __restrict__ out4)
{
    extern __shared__ float sm[];
    float* Ct_s  = sm;              // 4352
    float* Lr    = sm + 4352;       // 8704 (aliased as Mp)
    float* LLt   = sm + 13056;      // 8448
    float* u_s   = sm + 21504;      // 1024
    float* v_s   = sm + 22528;      // 1024
    float* U_s   = sm + 23552;      // 1040
    float* Fp_s  = sm + 24592;      // 1040
    float* w_s   = sm + 25632;      // 128
    float* wo_s  = sm + 25760;      // 256
    float* wo2   = sm + 26016;      // 256
    float* fb_s  = sm + 26272;      // 64
    float* fv2q  = sm + 26336;      // 512
    float* b2v   = sm + 26848;      // 8
    float* Mp = Lr;

    int bx = blockIdx.x;
    int b  = bx >> 1, ih = bx & 1;
    int tid = threadIdx.x;

    for (int idx = tid; idx < 4096; idx += NT2) {
        int e = idx >> 6, t = idx & 63;
        Ct_s[e*68 + t] = g_Ct[e*65 + t];
    }
    for (int idx = tid; idx < 1024; idx += NT2) {
        u_s[idx] = g_u_av[b*1024 + idx];
        v_s[idx] = g_v_av[b*1024 + idx];
        int r = idx >> 6, c = idx & 63;
        U_s [r*65 + c] = g_U  [b*1024 + idx];
        Fp_s[r*65 + c] = g_FmP[b*1024 + idx];
    }
    if (tid < 128) w_s[tid] = g_w[b*256 + ih*128 + tid];
    wo_s[tid] = g_wo[b*256 + tid];
    if (tid < 64)  fb_s[tid] = g_fb[tid];
    for (int idx = tid; idx < 512; idx += NT2)
        fv2q[idx] = fv2[(idx & 7)*64 + (idx >> 3)];
    if (tid < 8)   b2v[tid] = fv2b[tid];
    __syncthreads();
    {
        int j = tid >> 4, k = tid & 15;
        wo2[tid] = (k == j) ? 0.f : wo_s[tid];
    }
    for (int idx = tid; idx < 8192; idx += NT2) {
        int r = idx >> 6, e = idx & 63;
        int j = r & 15;
        Lr[r*68 + e] = leaky(fmaf(w_s[r], v_s[j*64 + e], u_s[j*64 + e]));
    }
    __syncthreads();
    // LL' build
    {
        int eg = tid & 7, rq = tid >> 3;
        int e0 = eg * 8;
        int i4 = rq >> 2;
        int j0 = (rq & 3) * 4;
        int rbase = i4*16 + j0;
        unsigned long long acc0[8], acc1[8];
        #pragma unroll
        for (int m = 0; m < 8; m++){ acc0[m] = 0ull; acc1[m] = 0ull; }
        #pragma unroll
        for (int k = 0; k < 16; k++) {
            float w00 = wo2[(j0+0)*16 + k], w01 = wo2[(j0+1)*16 + k];
            float w10 = wo2[(j0+2)*16 + k], w11 = wo2[(j0+3)*16 + k];
            unsigned long long wp0, wp1;
            PACK2(wp0, __float_as_uint(w00), __float_as_uint(w01));
            PACK2(wp1, __float_as_uint(w10), __float_as_uint(w11));
            const float* lrow = &Lr[(i4*16 + k)*68 + e0];
            float4 la = *reinterpret_cast<const float4*>(lrow);
            float4 lb = *reinterpret_cast<const float4*>(lrow + 4);
            float ls[8] = {la.x, la.y, la.z, la.w, lb.x, lb.y, lb.z, lb.w};
            #pragma unroll
            for (int m = 0; m < 8; m++) {
                unsigned long long lp;
                unsigned int lu = __float_as_uint(ls[m]);
                PACK2(lp, lu, lu);
                FMA2(acc0[m], lp, wp0);
                FMA2(acc1[m], lp, wp1);
            }
        }
        #pragma unroll
        for (int m = 0; m < 8; m++) {
            *reinterpret_cast<ulonglong2*>(&LLt[(e0 + m)*132 + rbase]) =
                make_ulonglong2(acc0[m], acc1[m]);
        }
    }
    __syncthreads();
    // M = LL' @ Ct -> Mp (aliases Lr; Lr reads complete before this barrier)
    {
        int tt = tid & 15, rg = tid >> 4;
        int t0 = tt * 4, r0 = rg * 8;
        unsigned long long acc[4][4];
        #pragma unroll
        for (int a = 0; a < 4; a++)
            #pragma unroll
            for (int k = 0; k < 4; k++) acc[a][k] = 0ull;
        #pragma unroll 2
        for (int e = 0; e < 64; e++) {
            float4 ct = *reinterpret_cast<const float4*>(&Ct_s[e*68 + t0]);
            ulonglong2 la = *reinterpret_cast<const ulonglong2*>(&LLt[e*132 + r0]);
            ulonglong2 lb = *reinterpret_cast<const ulonglong2*>(&LLt[e*132 + r0 + 4]);
            unsigned long long lp0 = la.x, lp1 = la.y, lp2 = lb.x, lp3 = lb.y;
            float cts[4] = {ct.x, ct.y, ct.z, ct.w};
            #pragma unroll
            for (int a = 0; a < 4; a++) {
                unsigned int wu = __float_as_uint(cts[a]);
                unsigned long long wp;
                PACK2(wp, wu, wu);
                FMA2(acc[a][0], lp0, wp);
                FMA2(acc[a][1], lp1, wp);
                FMA2(acc[a][2], lp2, wp);
                FMA2(acc[a][3], lp3, wp);
            }
        }
        __syncthreads();
        #pragma unroll
        for (int k = 0; k < 4; k++) {
            uint2 x0 = *reinterpret_cast<uint2*>(&acc[0][k]);
            uint2 x1 = *reinterpret_cast<uint2*>(&acc[1][k]);
            uint2 x2 = *reinterpret_cast<uint2*>(&acc[2][k]);
            uint2 x3 = *reinterpret_cast<uint2*>(&acc[3][k]);
            *reinterpret_cast<float4*>(&Mp[(r0 + 2*k)*68 + t0]) =
                make_float4(__uint_as_float(x0.x), __uint_as_float(x1.x),
                            __uint_as_float(x2.x), __uint_as_float(x3.x));
            *reinterpret_cast<float4*>(&Mp[(r0 + 2*k + 1)*68 + t0]) =
                make_float4(__uint_as_float(x0.y), __uint_as_float(x1.y),
                            __uint_as_float(x2.y), __uint_as_float(x3.y));
        }
    }
    __syncthreads();
    // value head
    {
        int p = tid >> 1, q = tid & 1;
        int i4 = p >> 4, j = p & 15;
        float wjj = wo_s[j*17];
        float vout[8];
        #pragma unroll
        for (int o = 0; o < 8; o++) vout[o] = 0.f;
        #pragma unroll 4
        for (int tt = 0; tt < 32; tt++) {
            int t = q*32 + tt;
            float Mv  = Mp[p*68 + t];
            float fbt = fb_s[t];
            float h = U_s[j*65 + t] + 0.0625f * (Mv + fbt + wjj * (Fp_s[j*65 + t] - fbt));
            float ht = leaky(h);
            float4 f0 = *reinterpret_cast<const float4*>(&fv2q[t*8]);
            float4 f1 = *reinterpret_cast<const float4*>(&fv2q[t*8 + 4]);
            vout[0] = fmaf(f0.x, ht, vout[0]);
            vout[1] = fmaf(f0.y, ht, vout[1]);
            vout[2] = fmaf(f0.z, ht, vout[2]);
            vout[3] = fmaf(f0.w, ht, vout[3]);
            vout[4] = fmaf(f1.x, ht, vout[4]);
            vout[5] = fmaf(f1.y, ht, vout[5]);
            vout[6] = fmaf(f1.z, ht, vout[6]);
            vout[7] = fmaf(f1.w, ht, vout[7]);
        }
        #pragma unroll
        for (int o = 0; o < 8; o++) vout[o] += __shfl_xor_sync(0xffffffffu, vout[o], 1);
        if (q == 0) {
            #pragma unroll
            for (int o = 0; o < 8; o++) vout[o] += b2v[o];
            int ig = ih*8 + i4;
            float4* dst = reinterpret_cast<float4*>(out_val + (size_t)(b*256 + ig*16 + j)*8);
            dst[0] = make_float4(vout[0], vout[1], vout[2], vout[3]);
            dst[1] = make_float4(vout[4], vout[5], vout[6], vout[7]);
        }
    }
    // weights_obsz half
    {
        const float4* wo4 = reinterpret_cast<const float4*>(wo_s);
        #pragma unroll
        for (int k = 0; k < 2; k++) {
            int q4 = ih*512 + k*256 + tid;
            out4[b*1024 + q4] = wo4[q4 & 63];
        }
    }
}

// ---------------- launcher ----------------
extern "C" void kernel_launch(void* const* d_in, const int* in_sizes, int n_in,
                              void* d_out, int out_size)
{
    const float* obs  = (const float*)d_in[0];
    const float* pol  = (const float*)d_in[1];
    const float* act  = (const float*)d_in[2];
    const float* kw1  = (const float*)d_in[3];  const float* kw1b = (const float*)d_in[4];
    const float* kw2  = (const float*)d_in[5];  const float* kw2b = (const float*)d_in[6];
    const float* qw1  = (const float*)d_in[7];  const float* qw1b = (const float*)d_in[8];
    const float* qw2  = (const float*)d_in[9];  const float* qw2b = (const float*)d_in[10];
    const float* ko1  = (const float*)d_in[11]; const float* ko1b = (const float*)d_in[12];
    const float* ko2  = (const float*)d_in[13]; const float* ko2b = (const float*)d_in[14];
    const float* qo1  = (const float*)d_in[15]; const float* qo1b = (const float*)d_in[16];
    const float* qo2  = (const float*)d_in[17]; const float* qo2b = (const float*)d_in[18];
    const float* av1  = (const float*)d_in[19]; const float* av1b = (const float*)d_in[20];
    const float* av2  = (const float*)d_in[21]; const float* av2b = (const float*)d_in[22];
    const float* fv1  = (const float*)d_in[23]; const float* fv1b = (const float*)d_in[24];
    const float* fv2  = (const float*)d_in[25]; const float* fv2b = (const float*)d_in[26];

    float* out      = (float*)d_out;
    float* out_val  = out;
    float* out_wz   = out + 262144;
    float* out_obsz = out + 294912;

    const int SM1 = 28944 * 4;   // 115776
    const int SM2 = 26856 * 4;   // 107424

    cudaFuncSetAttribute(L1, cudaFuncAttributeMaxDynamicSharedMemorySize, SM1);
    cudaFuncSetAttribute(L2, cudaFuncAttributeMaxDynamicSharedMemorySize, SM2);

    L1<<<129, NT1, SM1>>>(obs, pol, act,
                          kw1, kw1b, kw2, kw2b, qw1, qw1b, qw2, qw2b,
                          ko1, ko1b, ko2, ko2b, qo1, qo1b, qo2, qo2b,
                          av1, av1b, av2, av2b, fv1, fv1b, out_wz);
    L2<<<256, NT2, SM2>>>(fv2, fv2b, out_val,
                          reinterpret_cast<float4*>(out_obsz));
}